// round 2
// baseline (speedup 1.0000x reference)
#include <cuda_runtime.h>

#define NN 100000
#define NE 1600000
#define CH 64

// Scratch (device globals — no allocation allowed)
__device__ __align__(16) float g_q[NN*CH];
__device__ __align__(16) float g_k[NN*CH];
__device__ __align__(16) float g_v[NN*CH];
__device__ __align__(16) float g_skip[NN*CH];
__device__ __align__(16) float g_agg[NN*CH];
__device__ float g_den[NN];
__device__ double g_red[2];
__device__ int g_idx64;

__device__ __forceinline__ unsigned long long ffma2(unsigned long long a,
                                                    unsigned long long b,
                                                    unsigned long long c){
    unsigned long long d;
    asm("fma.rn.f32x2 %0, %1, %2, %3;" : "=l"(d) : "l"(a), "l"(b), "l"(c));
    return d;
}
__device__ __forceinline__ float hadd2(unsigned long long a){
    float x, y;
    asm("mov.b64 {%0, %1}, %2;" : "=f"(x), "=f"(y) : "l"(a));
    return x + y;
}

// ---------------------------------------------------------------------------
// Pass 0a: detect whether the edge index buffer is int64 or int32.
// int64 little-endian with values < 2^31: every odd 32-bit word is 0.
// int32 uniform [0, 1e5): P(64 odd words all zero) ~ 1e-320.
// ---------------------------------------------------------------------------
__global__ void k_detect(const unsigned int* __restrict__ ei32){
    if (threadIdx.x == 0 && blockIdx.x == 0){
        int all_hi_zero = 1;
        #pragma unroll 1
        for (int k = 0; k < 64; k++)
            if (ei32[2*k+1] != 0u){ all_hi_zero = 0; break; }
        g_idx64 = all_hi_zero;
    }
}

// ---------------------------------------------------------------------------
// Pass 0b: zero the per-call accumulators
// ---------------------------------------------------------------------------
__global__ void k_zero(){
    int i = blockIdx.x*blockDim.x + threadIdx.x;
    if (i < NN*CH/4) reinterpret_cast<float4*>(g_agg)[i] = make_float4(0.f,0.f,0.f,0.f);
    if (i < NN) g_den[i] = 0.f;
    if (i == 0){ g_red[0] = 0.0; g_red[1] = 0.0; }
}

// ---------------------------------------------------------------------------
// Pass 1: q = euc@Wq^T+bq, k = geo@Wk^T+bk, v = geo@Wv^T+bv, skip = euc@Ws^T+bs
// thread = (matrix m, out-channel c). Weight row held as 32 packed f32x2;
// x rows staged in smem and broadcast; fma.rn.f32x2 doubles fp32 rate.
// ---------------------------------------------------------------------------
__global__ void __launch_bounds__(256, 2) k_qkvs(
    const float* __restrict__ geo, const float* __restrict__ euc,
    const float* __restrict__ Wq, const float* __restrict__ bq,
    const float* __restrict__ Wk, const float* __restrict__ bk,
    const float* __restrict__ Wv, const float* __restrict__ bv,
    const float* __restrict__ Ws, const float* __restrict__ bs)
{
    const int tid = threadIdx.x;
    const int m = tid >> 6;
    const int c = tid & 63;
    const float* W = (m==0)?Wq:(m==1)?Wk:(m==2)?Wv:Ws;
    const float* B = (m==0)?bq:(m==1)?bk:(m==2)?bv:bs;
    float* OUT     = (m==0)?g_q:(m==1)?g_k:(m==2)?g_v:g_skip;
    const int use_euc = (m==0)||(m==3);

    unsigned long long w[32];
    {
        const unsigned long long* wr =
            reinterpret_cast<const unsigned long long*>(W + c*CH);
        #pragma unroll
        for (int i=0;i<32;i++) w[i] = wr[i];
    }
    const float bias = B[c];

    __shared__ unsigned long long sx[2][8*32];   // 8 nodes x 32 f32x2, euc/geo

    for (int tile = blockIdx.x*8; tile < NN; tile += gridDim.x*8){
        {
            float* se = reinterpret_cast<float*>(sx[0]);
            float* sg = reinterpret_cast<float*>(sx[1]);
            se[tid]       = euc[tile*CH + tid];
            se[tid + 256] = euc[tile*CH + tid + 256];
            sg[tid]       = geo[tile*CH + tid];
            sg[tid + 256] = geo[tile*CH + tid + 256];
        }
        __syncthreads();
        const unsigned long long* xs = use_euc ? sx[0] : sx[1];
        #pragma unroll
        for (int t=0;t<8;t++){
            const unsigned long long* xr = xs + t*32;
            unsigned long long a0=0ull, a1=0ull, a2=0ull, a3=0ull;
            #pragma unroll
            for (int i=0;i<32;i+=4){
                a0 = ffma2(xr[i+0], w[i+0], a0);
                a1 = ffma2(xr[i+1], w[i+1], a1);
                a2 = ffma2(xr[i+2], w[i+2], a2);
                a3 = ffma2(xr[i+3], w[i+3], a3);
            }
            float s = hadd2(a0)+hadd2(a1)+hadd2(a2)+hadd2(a3) + bias;
            OUT[(tile+t)*CH + c] = s;
        }
        __syncthreads();
    }
}

// ---------------------------------------------------------------------------
// Pass 2: single fused edge pass.
// 16 threads / edge. alpha = dot(q[dst],k[src])/8 (shfl tree over 16 lanes),
// ex = exp(alpha) (segment-max folded out: bounded logits, ratio invariant),
// denom[dst] += ex ; agg[dst] += ex * v[src]  (red.global.add.v4.f32)
// ---------------------------------------------------------------------------
__global__ void k_edge(const void* __restrict__ ei_raw){
    int gt  = blockIdx.x*blockDim.x + threadIdx.x;
    int e   = gt >> 4;
    int sub = threadIdx.x & 15;
    if (e >= NE) return;

    int src, dst;
    if (g_idx64){
        const long long* ei = (const long long*)ei_raw;
        src = (int)__ldg(ei + e);
        dst = (int)__ldg(ei + NE + e);
    } else {
        const int* ei = (const int*)ei_raw;
        src = __ldg(ei + e);
        dst = __ldg(ei + NE + e);
    }
    // safety clamp: OOB decode becomes wrong-value (rel_err), never a fault
    src = min(max(src, 0), NN-1);
    dst = min(max(dst, 0), NN-1);

    const float4 qv = *reinterpret_cast<const float4*>(g_q + (size_t)dst*CH + sub*4);
    const float4 kv = *reinterpret_cast<const float4*>(g_k + (size_t)src*CH + sub*4);
    float d = qv.x*kv.x + qv.y*kv.y + qv.z*kv.z + qv.w*kv.w;
    d += __shfl_xor_sync(0xffffffffu, d, 8);
    d += __shfl_xor_sync(0xffffffffu, d, 4);
    d += __shfl_xor_sync(0xffffffffu, d, 2);
    d += __shfl_xor_sync(0xffffffffu, d, 1);
    float ex = __expf(d * 0.125f);   // 1/sqrt(64)

    if (sub == 0) atomicAdd(g_den + dst, ex);
    const float4 vv = *reinterpret_cast<const float4*>(g_v + (size_t)src*CH + sub*4);
    float* addr = g_agg + (size_t)dst*CH + sub*4;
    asm volatile("red.global.add.v4.f32 [%0], {%1, %2, %3, %4};"
        :: "l"(addr), "f"(ex*vv.x), "f"(ex*vv.y), "f"(ex*vv.z), "f"(ex*vv.w)
        : "memory");
}

// ---------------------------------------------------------------------------
// Pass 3: out_pre = agg/(denom+1e-16) + skip ; accumulate global sum, sumsq
// ---------------------------------------------------------------------------
__global__ void k_final1(float* __restrict__ out){
    float lsum = 0.f, lsq = 0.f;
    for (int i = blockIdx.x*blockDim.x + threadIdx.x; i < NN*CH;
         i += gridDim.x*blockDim.x){
        float val = g_agg[i] / (g_den[i>>6] + 1e-16f) + g_skip[i];
        out[i] = val;
        lsum += val;
        lsq  += val*val;
    }
    #pragma unroll
    for (int off=16; off>0; off>>=1){
        lsum += __shfl_xor_sync(0xffffffffu, lsum, off);
        lsq  += __shfl_xor_sync(0xffffffffu, lsq,  off);
    }
    __shared__ float s1[8], s2[8];
    int wid = threadIdx.x >> 5;
    if ((threadIdx.x & 31) == 0){ s1[wid] = lsum; s2[wid] = lsq; }
    __syncthreads();
    if (threadIdx.x == 0){
        float ts = 0.f, tq = 0.f;
        #pragma unroll
        for (int i=0;i<8;i++){ ts += s1[i]; tq += s2[i]; }
        atomicAdd(&g_red[0], (double)ts);
        atomicAdd(&g_red[1], (double)tq);
    }
}

// ---------------------------------------------------------------------------
// Pass 4: graph layernorm + relu
// ---------------------------------------------------------------------------
__global__ void k_final2(float* __restrict__ out,
                         const float* __restrict__ lnw,
                         const float* __restrict__ lnb){
    int i = blockIdx.x*blockDim.x + threadIdx.x;
    if (i >= NN*CH) return;
    const double invM = 1.0 / (double)(NN*CH);
    float mean = (float)(g_red[0]*invM);
    float var  = (float)(g_red[1]*invM) - mean*mean;
    float stdv = sqrtf(fmaxf(var, 0.f));
    float x = out[i];
    float y = (x - mean) / (stdv + 1e-5f) * lnw[i & 63] + lnb[i & 63];
    out[i] = y > 0.f ? y : 0.f;
}

// ---------------------------------------------------------------------------
extern "C" void kernel_launch(void* const* d_in, const int* in_sizes, int n_in,
                              void* d_out, int out_size){
    const float* geo = (const float*)d_in[0];
    const float* euc = (const float*)d_in[1];
    const float* Wq  = (const float*)d_in[2];
    const float* bq  = (const float*)d_in[3];
    const float* Wk  = (const float*)d_in[4];
    const float* bk  = (const float*)d_in[5];
    const float* Wv  = (const float*)d_in[6];
    const float* bv  = (const float*)d_in[7];
    const float* Ws  = (const float*)d_in[8];
    const float* bs  = (const float*)d_in[9];
    const float* lnw = (const float*)d_in[10];
    const float* lnb = (const float*)d_in[11];

    // locate edge_index defensively: the input with 2*E elements
    const void* ei = d_in[12];
    for (int i = 0; i < n_in; i++)
        if (in_sizes[i] == 2*NE){ ei = d_in[i]; break; }

    float* out = (float*)d_out;

    k_detect<<<1, 32>>>((const unsigned int*)ei);
    k_zero  <<<(NN*CH/4 + 255)/256, 256>>>();
    k_qkvs  <<<592, 256>>>(geo, euc, Wq, bq, Wk, bk, Wv, bv, Ws, bs);
    k_edge  <<<(NE*16 + 255)/256, 256>>>(ei);
    k_final1<<<592, 256>>>(out);
    k_final2<<<(NN*CH + 255)/256, 256>>>(out, lnw, lnb);
}

// round 3
// speedup vs baseline: 1.5330x; 1.5330x over previous
#include <cuda_runtime.h>

#define NN 100000
#define NE 1600000
#define CH 64

typedef unsigned long long ull;

// Scratch (device globals — no allocation allowed)
__device__ __align__(16) float g_q[NN*CH];
__device__ __align__(16) float g_k[NN*CH];
__device__ __align__(16) float g_v[NN*CH];
__device__ __align__(16) float g_skip[NN*CH];
__device__ __align__(16) float g_agg[NN*CH];
__device__ float g_den[NN];
__device__ double g_red[2];
__device__ int g_idx64;

__device__ __forceinline__ ull ffma2(ull a, ull b, ull c){
    ull d;
    asm("fma.rn.f32x2 %0, %1, %2, %3;" : "=l"(d) : "l"(a), "l"(b), "l"(c));
    return d;
}
__device__ __forceinline__ float hadd2(ull a){
    float x, y;
    asm("mov.b64 {%0, %1}, %2;" : "=f"(x), "=f"(y) : "l"(a));
    return x + y;
}

// ---------------------------------------------------------------------------
// Pass 1 (launched FIRST): fused q/k/v/skip GEMM + zero agg/den/red.
// thread = (matrix m, out-channel c); weight row in 32 packed-f32x2 regs;
// 16-node x-tiles double-buffered in smem with register prefetch; LDS.128.
// grid MUST be 625 (625*16*10 = 100000, exact).
// ---------------------------------------------------------------------------
__global__ void __launch_bounds__(256, 2) k_qkvs(
    const float* __restrict__ geo, const float* __restrict__ euc,
    const float* __restrict__ Wq, const float* __restrict__ bq,
    const float* __restrict__ Wk, const float* __restrict__ bk,
    const float* __restrict__ Wv, const float* __restrict__ bv,
    const float* __restrict__ Ws, const float* __restrict__ bs)
{
    const int tid = threadIdx.x;
    const int m = tid >> 6;
    const int c = tid & 63;
    const float* W = (m==0)?Wq:(m==1)?Wk:(m==2)?Wv:Ws;
    const float* B = (m==0)?bq:(m==1)?bk:(m==2)?bv:bs;
    float* OUT     = (m==0)?g_q:(m==1)?g_k:(m==2)?g_v:g_skip;
    const int use_euc = (m==0)||(m==3);

    if (blockIdx.x == 0 && tid == 0){ g_red[0] = 0.0; g_red[1] = 0.0; }

    ull w[32];
    {
        const ull* wr = reinterpret_cast<const ull*>(W + c*CH);
        #pragma unroll
        for (int i=0;i<32;i++) w[i] = wr[i];
    }
    const float bias = B[c];

    // [buf][euc/geo][16 nodes * 32 f32x2] = 16KB
    __shared__ ull sx[2][2][16*32];

    const int base = blockIdx.x * 16;
    float4 pe = *reinterpret_cast<const float4*>(euc + base*CH + tid*4);
    float4 pg = *reinterpret_cast<const float4*>(geo + base*CH + tid*4);

    #pragma unroll 1
    for (int it = 0; it < 10; it++){
        const int tile = base + it*10000;
        const int buf = it & 1;
        reinterpret_cast<float4*>(sx[buf][0])[tid] = pe;
        reinterpret_cast<float4*>(sx[buf][1])[tid] = pg;
        __syncthreads();
        if (it < 9){
            const int nt = tile + 10000;
            pe = *reinterpret_cast<const float4*>(euc + nt*CH + tid*4);
            pg = *reinterpret_cast<const float4*>(geo + nt*CH + tid*4);
        }
        // zero the per-call accumulators for this tile (replaces k_zero)
        reinterpret_cast<float4*>(g_agg + (size_t)tile*CH)[tid] =
            make_float4(0.f,0.f,0.f,0.f);
        if (tid < 16) g_den[tile + tid] = 0.f;

        const ull* xs = sx[buf][use_euc ? 0 : 1];
        #pragma unroll
        for (int t=0;t<16;t++){
            const ulonglong2* xr = reinterpret_cast<const ulonglong2*>(xs + t*32);
            ull a0=0ull, a1=0ull, a2=0ull, a3=0ull;
            #pragma unroll
            for (int i=0;i<16;i+=2){
                ulonglong2 x0 = xr[i];
                ulonglong2 x1 = xr[i+1];
                a0 = ffma2(x0.x, w[2*i+0], a0);
                a1 = ffma2(x0.y, w[2*i+1], a1);
                a2 = ffma2(x1.x, w[2*i+2], a2);
                a3 = ffma2(x1.y, w[2*i+3], a3);
            }
            OUT[(size_t)(tile+t)*CH + c] =
                hadd2(a0)+hadd2(a1)+hadd2(a2)+hadd2(a3) + bias;
        }
        // double buffer: next STS targets the other buffer; sync above suffices
    }
}

// ---------------------------------------------------------------------------
// Pass 2: dtype detect (parallel, 1 warp). int64 LE with values < 2^31 has
// all odd 32-bit words zero; int32 uniform [0,1e5): P(32 zeros) ~ 1e-160.
// ---------------------------------------------------------------------------
__global__ void k_detect(const unsigned int* __restrict__ ei32){
    unsigned int hi = ei32[2*threadIdx.x + 1];
    unsigned int b = __ballot_sync(0xffffffffu, hi != 0u);
    if (threadIdx.x == 0) g_idx64 = (b == 0u);
}

// ---------------------------------------------------------------------------
// Pass 3: fused edge pass, 4 lanes/edge.
// All q/k/v gathers issued up-front (MLP=12), 2-level shfl dot reduce,
// ex = exp(alpha) (segment-max folded: bounded logits, softmax invariant),
// den[dst] += ex ; agg[dst] += ex * v[src] via red.global.add.v4.f32.
// ---------------------------------------------------------------------------
__global__ void k_edge(const void* __restrict__ ei_raw){
    const int gt  = blockIdx.x*blockDim.x + threadIdx.x;
    const int e   = gt >> 2;
    const int sub = threadIdx.x & 3;

    int src, dst;
    if (g_idx64){
        const long long* ei = (const long long*)ei_raw;
        src = (int)__ldg(ei + e);
        dst = (int)__ldg(ei + NE + e);
    } else {
        const int* ei = (const int*)ei_raw;
        src = __ldg(ei + e);
        dst = __ldg(ei + NE + e);
    }
    // safety clamp: OOB decode becomes rel_err, never a fault
    src = min(max(src, 0), NN-1);
    dst = min(max(dst, 0), NN-1);

    const float4* qp = reinterpret_cast<const float4*>(g_q) + (size_t)dst*16;
    const float4* kp = reinterpret_cast<const float4*>(g_k) + (size_t)src*16;
    const float4* vp = reinterpret_cast<const float4*>(g_v) + (size_t)src*16;

    float4 q0 = qp[sub],   q1 = qp[sub+4],  q2 = qp[sub+8],  q3 = qp[sub+12];
    float4 k0 = kp[sub],   k1 = kp[sub+4],  k2 = kp[sub+8],  k3 = kp[sub+12];
    float4 v0 = vp[sub],   v1 = vp[sub+4],  v2 = vp[sub+8],  v3 = vp[sub+12];

    float d = q0.x*k0.x + q0.y*k0.y + q0.z*k0.z + q0.w*k0.w
            + q1.x*k1.x + q1.y*k1.y + q1.z*k1.z + q1.w*k1.w
            + q2.x*k2.x + q2.y*k2.y + q2.z*k2.z + q2.w*k2.w
            + q3.x*k3.x + q3.y*k3.y + q3.z*k3.z + q3.w*k3.w;
    d += __shfl_xor_sync(0xffffffffu, d, 2);
    d += __shfl_xor_sync(0xffffffffu, d, 1);
    const float ex = __expf(d * 0.125f);   // 1/sqrt(64)

    if (sub == 0) atomicAdd(g_den + dst, ex);

    float* ap = g_agg + (size_t)dst*CH;
    asm volatile("red.global.add.v4.f32 [%0], {%1, %2, %3, %4};"
        :: "l"(ap + sub*4),      "f"(ex*v0.x), "f"(ex*v0.y), "f"(ex*v0.z), "f"(ex*v0.w) : "memory");
    asm volatile("red.global.add.v4.f32 [%0], {%1, %2, %3, %4};"
        :: "l"(ap + 16 + sub*4), "f"(ex*v1.x), "f"(ex*v1.y), "f"(ex*v1.z), "f"(ex*v1.w) : "memory");
    asm volatile("red.global.add.v4.f32 [%0], {%1, %2, %3, %4};"
        :: "l"(ap + 32 + sub*4), "f"(ex*v2.x), "f"(ex*v2.y), "f"(ex*v2.z), "f"(ex*v2.w) : "memory");
    asm volatile("red.global.add.v4.f32 [%0], {%1, %2, %3, %4};"
        :: "l"(ap + 48 + sub*4), "f"(ex*v3.x), "f"(ex*v3.y), "f"(ex*v3.z), "f"(ex*v3.w) : "memory");
}

// ---------------------------------------------------------------------------
// Pass 4: out_pre = agg/(den+1e-16) + skip ; accumulate global sum/sumsq
// ---------------------------------------------------------------------------
__global__ void k_final1(float* __restrict__ out){
    float lsum = 0.f, lsq = 0.f;
    const float4* agg4  = reinterpret_cast<const float4*>(g_agg);
    const float4* skip4 = reinterpret_cast<const float4*>(g_skip);
    float4* out4 = reinterpret_cast<float4*>(out);
    for (int i = blockIdx.x*blockDim.x + threadIdx.x; i < NN*16;
         i += gridDim.x*blockDim.x){
        float4 a = agg4[i];
        float4 s = skip4[i];
        const float inv = 1.f / (g_den[i>>4] + 1e-16f);
        float4 val;
        val.x = a.x*inv + s.x;  val.y = a.y*inv + s.y;
        val.z = a.z*inv + s.z;  val.w = a.w*inv + s.w;
        out4[i] = val;
        lsum += val.x + val.y + val.z + val.w;
        lsq  += val.x*val.x + val.y*val.y + val.z*val.z + val.w*val.w;
    }
    #pragma unroll
    for (int off=16; off>0; off>>=1){
        lsum += __shfl_xor_sync(0xffffffffu, lsum, off);
        lsq  += __shfl_xor_sync(0xffffffffu, lsq,  off);
    }
    __shared__ float s1[8], s2[8];
    const int wid = threadIdx.x >> 5;
    if ((threadIdx.x & 31) == 0){ s1[wid] = lsum; s2[wid] = lsq; }
    __syncthreads();
    if (threadIdx.x == 0){
        float ts = 0.f, tq = 0.f;
        #pragma unroll
        for (int i=0;i<8;i++){ ts += s1[i]; tq += s2[i]; }
        atomicAdd(&g_red[0], (double)ts);
        atomicAdd(&g_red[1], (double)tq);
    }
}

// ---------------------------------------------------------------------------
// Pass 5: graph layernorm + relu
// ---------------------------------------------------------------------------
__global__ void k_final2(float* __restrict__ out,
                         const float* __restrict__ lnw,
                         const float* __restrict__ lnb){
    const int i = blockIdx.x*blockDim.x + threadIdx.x;
    if (i >= NN*16) return;
    const double invM = 1.0 / (double)(NN*CH);
    const float mean = (float)(g_red[0]*invM);
    const float var  = (float)(g_red[1]*invM) - mean*mean;
    const float rstd = 1.f / (sqrtf(fmaxf(var, 0.f)) + 1e-5f);
    const int cb = (i & 15) * 4;
    const float4 wv = *reinterpret_cast<const float4*>(lnw + cb);
    const float4 bv = *reinterpret_cast<const float4*>(lnb + cb);
    float4 x = reinterpret_cast<float4*>(out)[i];
    float4 y;
    y.x = fmaxf((x.x - mean)*rstd*wv.x + bv.x, 0.f);
    y.y = fmaxf((x.y - mean)*rstd*wv.y + bv.y, 0.f);
    y.z = fmaxf((x.z - mean)*rstd*wv.z + bv.z, 0.f);
    y.w = fmaxf((x.w - mean)*rstd*wv.w + bv.w, 0.f);
    reinterpret_cast<float4*>(out)[i] = y;
}

// ---------------------------------------------------------------------------
extern "C" void kernel_launch(void* const* d_in, const int* in_sizes, int n_in,
                              void* d_out, int out_size){
    const float* geo = (const float*)d_in[0];
    const float* euc = (const float*)d_in[1];
    const float* Wq  = (const float*)d_in[2];
    const float* bq  = (const float*)d_in[3];
    const float* Wk  = (const float*)d_in[4];
    const float* bk  = (const float*)d_in[5];
    const float* Wv  = (const float*)d_in[6];
    const float* bv  = (const float*)d_in[7];
    const float* Ws  = (const float*)d_in[8];
    const float* bs  = (const float*)d_in[9];
    const float* lnw = (const float*)d_in[10];
    const float* lnb = (const float*)d_in[11];

    // locate edge_index defensively: the input with 2*E elements
    const void* ei = d_in[12];
    for (int i = 0; i < n_in; i++)
        if (in_sizes[i] == 2*NE){ ei = d_in[i]; break; }

    float* out = (float*)d_out;

    k_qkvs  <<<625, 256>>>(geo, euc, Wq, bq, Wk, bk, Wv, bv, Ws, bs);
    k_detect<<<1, 32>>>((const unsigned int*)ei);
    k_edge  <<<NE*4/256, 256>>>(ei);
    k_final1<<<592, 256>>>(out);
    k_final2<<<(NN*16 + 255)/256, 256>>>(out, lnw, lnb);
}